// round 3
// baseline (speedup 1.0000x reference)
#include <cuda_runtime.h>

// MaxPool2d: kernel=2, stride=2, padding=0
// Input:  (32, 64, 224, 224) fp32  -> NC = 2048 planes of 224x224
// Output: (32, 64, 112, 112) fp32
//
// R2: 8 outputs per thread (8 front-batched LDG.128, 2 STG.128),
//     32-bit index math with constant divisors, streaming cache hints.

#define IN_H    224
#define IN_W    224
#define OUT_H   112
#define OUT_W   112
#define NC      (32 * 64)

// Each thread handles 8 consecutive output columns (two float4 stores).
// OUT_W / 8 = 14 groups per output row.
#define OW8     (OUT_W / 8)
// total threads = NC * OUT_H * OW8 = 2048 * 112 * 14 = 3,211,264  (fits 32-bit)
#define TOTAL   (NC * OUT_H * OW8)

__global__ __launch_bounds__(256)
void maxpool2d_k2s2_kernel(const float* __restrict__ in,
                           float* __restrict__ out)
{
    const unsigned idx = blockIdx.x * blockDim.x + threadIdx.x;
    if (idx >= (unsigned)TOTAL) return;

    // 32-bit div/mod by compile-time constants -> magic-multiply IMADs
    const unsigned ow8 = idx % OW8;
    const unsigned tmp = idx / OW8;
    const unsigned oh  = tmp % OUT_H;
    const unsigned nc  = tmp / OUT_H;

    const float* row0 = in + (size_t)nc * (IN_H * IN_W)
                           + (size_t)(2u * oh) * IN_W
                           + ow8 * 16u;
    const float* row1 = row0 + IN_W;

    // 8 independent 128-bit streaming loads, front-batched (MLP=8)
    const float4 a0 = __ldcs(reinterpret_cast<const float4*>(row0));
    const float4 a1 = __ldcs(reinterpret_cast<const float4*>(row0 + 4));
    const float4 a2 = __ldcs(reinterpret_cast<const float4*>(row0 + 8));
    const float4 a3 = __ldcs(reinterpret_cast<const float4*>(row0 + 12));
    const float4 b0 = __ldcs(reinterpret_cast<const float4*>(row1));
    const float4 b1 = __ldcs(reinterpret_cast<const float4*>(row1 + 4));
    const float4 b2 = __ldcs(reinterpret_cast<const float4*>(row1 + 8));
    const float4 b3 = __ldcs(reinterpret_cast<const float4*>(row1 + 12));

    float4 o0, o1;
    o0.x = fmaxf(fmaxf(a0.x, a0.y), fmaxf(b0.x, b0.y));
    o0.y = fmaxf(fmaxf(a0.z, a0.w), fmaxf(b0.z, b0.w));
    o0.z = fmaxf(fmaxf(a1.x, a1.y), fmaxf(b1.x, b1.y));
    o0.w = fmaxf(fmaxf(a1.z, a1.w), fmaxf(b1.z, b1.w));
    o1.x = fmaxf(fmaxf(a2.x, a2.y), fmaxf(b2.x, b2.y));
    o1.y = fmaxf(fmaxf(a2.z, a2.w), fmaxf(b2.z, b2.w));
    o1.z = fmaxf(fmaxf(a3.x, a3.y), fmaxf(b3.x, b3.y));
    o1.w = fmaxf(fmaxf(a3.z, a3.w), fmaxf(b3.z, b3.w));

    float* outp = out + (size_t)nc * (OUT_H * OUT_W)
                      + (size_t)oh * OUT_W
                      + ow8 * 8u;
    __stcs(reinterpret_cast<float4*>(outp),     o0);
    __stcs(reinterpret_cast<float4*>(outp + 4), o1);
}

extern "C" void kernel_launch(void* const* d_in, const int* in_sizes, int n_in,
                              void* d_out, int out_size)
{
    const float* x = (const float*)d_in[0];
    float* y = (float*)d_out;

    const int block = 256;
    const int grid = (TOTAL + block - 1) / block;   // 12544

    maxpool2d_k2s2_kernel<<<grid, block>>>(x, y);
}

// round 4
// speedup vs baseline: 1.0017x; 1.0017x over previous
#include <cuda_runtime.h>

// MaxPool2d: kernel=2, stride=2, padding=0
// Input:  (32, 64, 224, 224) fp32  -> NC = 2048 planes of 224x224
// Output: (32, 64, 112, 112) fp32
//
// R3: R1's coalesced layout (each thread = one float4 output group,
//     consecutive lanes -> consecutive 16B) + MLP=8 via 2 warp-strided
//     groups per thread. No tail (TOTAL % 512 == 0), streaming hints.

#define IN_H    224
#define IN_W    224
#define OUT_H   112
#define OUT_W   112
#define NC      (32 * 64)

#define OW4     (OUT_W / 4)                 // 28 float4 groups per output row
#define TOTAL   (NC * OUT_H * OW4)          // 6,422,528 groups; % 512 == 0

__device__ __forceinline__ void decode(unsigned g,
                                       const float** row0,
                                       float** outp,
                                       const float* __restrict__ in,
                                       float* __restrict__ out)
{
    const unsigned ow4 = g % OW4;
    const unsigned tmp = g / OW4;
    const unsigned oh  = tmp % OUT_H;
    const unsigned nc  = tmp / OUT_H;

    *row0 = in  + (size_t)nc * (IN_H * IN_W) + (size_t)(2u * oh) * IN_W + ow4 * 8u;
    *outp = out + (size_t)nc * (OUT_H * OUT_W) + (size_t)oh * OUT_W + ow4 * 4u;
}

__global__ __launch_bounds__(256)
void maxpool2d_k2s2_kernel(const float* __restrict__ in,
                           float* __restrict__ out)
{
    const unsigned base = blockIdx.x * 512u + threadIdx.x;
    const unsigned g0 = base;          // group 0: lanes hit consecutive 16B
    const unsigned g1 = base + 256u;   // group 1: same, warp-strided

    const float *p0, *p1;
    float *q0, *q1;
    decode(g0, &p0, &q0, in, out);
    decode(g1, &p1, &q1, in, out);

    // 8 independent 128-bit streaming loads, front-batched (MLP=8)
    const float4 a0 = __ldcs(reinterpret_cast<const float4*>(p0));
    const float4 a1 = __ldcs(reinterpret_cast<const float4*>(p0 + 4));
    const float4 b0 = __ldcs(reinterpret_cast<const float4*>(p0 + IN_W));
    const float4 b1 = __ldcs(reinterpret_cast<const float4*>(p0 + IN_W + 4));
    const float4 c0 = __ldcs(reinterpret_cast<const float4*>(p1));
    const float4 c1 = __ldcs(reinterpret_cast<const float4*>(p1 + 4));
    const float4 d0 = __ldcs(reinterpret_cast<const float4*>(p1 + IN_W));
    const float4 d1 = __ldcs(reinterpret_cast<const float4*>(p1 + IN_W + 4));

    float4 o0, o1;
    o0.x = fmaxf(fmaxf(a0.x, a0.y), fmaxf(b0.x, b0.y));
    o0.y = fmaxf(fmaxf(a0.z, a0.w), fmaxf(b0.z, b0.w));
    o0.z = fmaxf(fmaxf(a1.x, a1.y), fmaxf(b1.x, b1.y));
    o0.w = fmaxf(fmaxf(a1.z, a1.w), fmaxf(b1.z, b1.w));
    o1.x = fmaxf(fmaxf(c0.x, c0.y), fmaxf(d0.x, d0.y));
    o1.y = fmaxf(fmaxf(c0.z, c0.w), fmaxf(d0.z, d0.w));
    o1.z = fmaxf(fmaxf(c1.x, c1.y), fmaxf(d1.x, d1.y));
    o1.w = fmaxf(fmaxf(c1.z, c1.w), fmaxf(d1.z, d1.w));

    __stcs(reinterpret_cast<float4*>(q0), o0);
    __stcs(reinterpret_cast<float4*>(q1), o1);
}

extern "C" void kernel_launch(void* const* d_in, const int* in_sizes, int n_in,
                              void* d_out, int out_size)
{
    const float* x = (const float*)d_in[0];
    float* y = (float*)d_out;

    const int block = 256;
    const int grid = TOTAL / 512;   // 12544, exact

    maxpool2d_k2s2_kernel<<<grid, block>>>(x, y);
}

// round 5
// speedup vs baseline: 1.0118x; 1.0101x over previous
#include <cuda_runtime.h>

// MaxPool2d: kernel=2, stride=2, padding=0
// Input:  (32, 64, 224, 224) fp32  -> NC = 2048 planes of 224x224
// Output: (32, 64, 112, 112) fp32
//
// R4: R1's access pattern (1 float4 output group per thread, MLP=4,
//     plain cached loads/stores) with a minimal prologue:
//     32-bit constant-divisor index math, no bounds check (no tail:
//     TOTAL == 25088 * 256 exactly), no cache hints.

#define IN_H    224
#define IN_W    224
#define OUT_H   112
#define OUT_W   112
#define NC      (32 * 64)

#define OW4     (OUT_W / 4)                 // 28 float4 groups per output row
#define TOTAL   (NC * OUT_H * OW4)          // 6,422,528 == 25088 * 256

__global__ __launch_bounds__(256)
void maxpool2d_k2s2_kernel(const float* __restrict__ in,
                           float* __restrict__ out)
{
    const unsigned idx = blockIdx.x * 256u + threadIdx.x;   // no tail, no guard

    // 32-bit div/mod by constants -> magic-multiply IMADs (no subroutine call)
    const unsigned ow4 = idx % OW4;
    const unsigned tmp = idx / OW4;
    const unsigned oh  = tmp % OUT_H;
    const unsigned nc  = tmp / OUT_H;

    const float* row0 = in + (size_t)nc * (IN_H * IN_W)
                           + (size_t)(2u * oh) * IN_W
                           + ow4 * 8u;
    const float* row1 = row0 + IN_W;

    // 4 independent 128-bit loads, front-batched (MLP=4), default caching
    const float4 a0 = *reinterpret_cast<const float4*>(row0);
    const float4 a1 = *reinterpret_cast<const float4*>(row0 + 4);
    const float4 b0 = *reinterpret_cast<const float4*>(row1);
    const float4 b1 = *reinterpret_cast<const float4*>(row1 + 4);

    float4 o;
    o.x = fmaxf(fmaxf(a0.x, a0.y), fmaxf(b0.x, b0.y));
    o.y = fmaxf(fmaxf(a0.z, a0.w), fmaxf(b0.z, b0.w));
    o.z = fmaxf(fmaxf(a1.x, a1.y), fmaxf(b1.x, b1.y));
    o.w = fmaxf(fmaxf(a1.z, a1.w), fmaxf(b1.z, b1.w));

    float* outp = out + (size_t)nc * (OUT_H * OUT_W)
                      + (size_t)oh * OUT_W
                      + ow4 * 4u;
    *reinterpret_cast<float4*>(outp) = o;
}

extern "C" void kernel_launch(void* const* d_in, const int* in_sizes, int n_in,
                              void* d_out, int out_size)
{
    const float* x = (const float*)d_in[0];
    float* y = (float*)d_out;

    maxpool2d_k2s2_kernel<<<TOTAL / 256, 256>>>(x, y);   // 25088 blocks, exact
}